// round 10
// baseline (speedup 1.0000x reference)
#include <cuda_runtime.h>
#include <cuda_bf16.h>
#include <math.h>
#include <stdint.h>

#define TN  256
#define BN  512
#define INN 128
#define MN  256
#define KC  640          // fused K: 128 x + 2*256 children
#define NW  96           // N tile: 32 m * 3 gates
#define GRID_P 296
#define SP  40           // padded smem row stride (bf16)

// dynamic smem: 3 stages * 35840B; stage layout: Ahi 0, Alo 10240, Bhi 20480, Blo 28160
#define STG 35840
#define NSTAGE 3
#define DSM (NSTAGE * STG)

// -------- device scratch --------
__device__ __nv_bfloat16 g_Wchi[768 * KC];   // fused weights [n'=3m+g][k]
__device__ __nv_bfloat16 g_Wclo[768 * KC];
__device__ __nv_bfloat16 g_Xhi[(size_t)TN * BN * INN];
__device__ __nv_bfloat16 g_Xlo[(size_t)TN * BN * INN];
__device__ __nv_bfloat16 g_Hhi[(size_t)TN * BN * MN];
__device__ __nv_bfloat16 g_Hlo[(size_t)TN * BN * MN];
__device__ float g_bc[768];                  // interleaved bias
__device__ int   g_child0[TN * BN];
__device__ int   g_child1[TN * BN];
__device__ int   g_root[BN];
__device__ int   g_order[TN];
__device__ int   g_lvlstart[TN + 2];
__device__ int   g_numlevels;
__device__ unsigned g_barcnt;

__device__ __forceinline__ float sigf(float x) { return 1.0f / (1.0f + expf(-x)); }

__device__ __forceinline__ uint32_t smem_u32(const void* p) {
    uint32_t a;
    asm("{ .reg .u64 t; cvta.to.shared.u64 t, %1; cvt.u32.u64 %0, t; }" : "=r"(a) : "l"(p));
    return a;
}

__device__ __forceinline__ void mma16816(float* d, const uint32_t* a, const uint32_t* b) {
    asm volatile(
        "mma.sync.aligned.m16n8k16.row.col.f32.bf16.bf16.f32 "
        "{%0,%1,%2,%3}, {%4,%5,%6,%7}, {%8,%9}, {%0,%1,%2,%3};"
        : "+f"(d[0]), "+f"(d[1]), "+f"(d[2]), "+f"(d[3])
        : "r"(a[0]), "r"(a[1]), "r"(a[2]), "r"(a[3]), "r"(b[0]), "r"(b[1]));
}

__device__ __forceinline__ void ldsm4(uint32_t* r, uint32_t addr) {
    asm volatile("ldmatrix.sync.aligned.m8n8.x4.shared.b16 {%0,%1,%2,%3}, [%4];"
                 : "=r"(r[0]), "=r"(r[1]), "=r"(r[2]), "=r"(r[3]) : "r"(addr));
}

__device__ __forceinline__ void cpa16(uint32_t dst, const void* src, int sz) {
    asm volatile("cp.async.ca.shared.global [%0], [%1], 16, %2;"
                 :: "r"(dst), "l"(src), "r"(sz) : "memory");
}
__device__ __forceinline__ void cpa_commit() {
    asm volatile("cp.async.commit_group;" ::: "memory");
}
__device__ __forceinline__ void cpa_wait1() {
    asm volatile("cp.async.wait_group 1;" ::: "memory");
}
__device__ __forceinline__ void cpa_wait0() {
    asm volatile("cp.async.wait_group 0;" ::: "memory");
}

__device__ __forceinline__ uint32_t packbf2(float x, float y) {
    __nv_bfloat162 v = __floats2bfloat162_rn(x, y);
    return *reinterpret_cast<uint32_t*>(&v);
}

// -------- prep: X split, fused interleaved weights, bias --------
__global__ void prep_kernel(const float* __restrict__ X,
                            const float* __restrict__ Wi, const float* __restrict__ bi,
                            const float* __restrict__ Wo, const float* __restrict__ bo,
                            const float* __restrict__ Wu, const float* __restrict__ bu,
                            const float* __restrict__ Ui, const float* __restrict__ Uo,
                            const float* __restrict__ Uu) {
    size_t idx = blockIdx.x * blockDim.x + threadIdx.x;
    size_t stride = (size_t)gridDim.x * blockDim.x;
    for (size_t i = idx; i < (size_t)TN * BN * INN; i += stride) {
        float x = X[i];
        __nv_bfloat16 h = __float2bfloat16_rn(x);
        g_Xhi[i] = h;
        g_Xlo[i] = __float2bfloat16_rn(x - __bfloat162float(h));
    }
    for (size_t i = idx; i < (size_t)768 * KC; i += stride) {
        int n = (int)(i / KC);
        int k = (int)(i % KC);
        int m = n / 3;
        int g = n % 3;
        float x;
        if (k < INN) {
            const float* W = (g == 0) ? Wi : ((g == 1) ? Wo : Wu);
            x = W[m * INN + k];
        } else {
            const float* U = (g == 0) ? Ui : ((g == 1) ? Uo : Uu);
            int br = (k - INN) / MN;
            int kk = (k - INN) % MN;
            x = U[br * MN * MN + m * MN + kk];
        }
        __nv_bfloat16 h = __float2bfloat16_rn(x);
        g_Wchi[i] = h;
        g_Wclo[i] = __float2bfloat16_rn(x - __bfloat162float(h));
    }
    for (size_t i = idx; i < 768; i += stride) {
        int m = (int)i / 3;
        int g = (int)i % 3;
        const float* bb = (g == 0) ? bi : ((g == 1) ? bo : bu);
        g_bc[i] = bb[m];
    }
}

// -------- scheduler --------
__global__ void sched_kernel(const int* __restrict__ arities) {
    __shared__ int s_lvl[TN];
    __shared__ int s_start[TN + 1];
    __shared__ int s_cur[TN + 1];
    __shared__ int s_max;
    int b = threadIdx.x;
    for (int i = b; i < TN; i += BN) s_lvl[i] = 0;
    for (int i = b; i < TN + 1; i += BN) s_cur[i] = 0;
    if (b == 0) { s_max = 0; g_barcnt = 0u; }
    __syncthreads();

    int stck[TN + 2];
    int lvl[TN];
    for (int i = 0; i < TN + 2; i++) stck[i] = 0;
    int sp = 1;
    for (int t = 0; t < TN; t++) {
        int a = arities[t * BN + b];
        int c0 = -1;
        int c1 = -1;
        if (a > 0) {
            int s = stck[max(sp, 0)];
            if (s < t) c0 = s;
        }
        if (a > 1) {
            int s = stck[max(sp - 1, 0)];
            if (s < t) c1 = s;
        }
        g_child0[t * BN + b] = c0;
        g_child1[t * BN + b] = c1;
        int L = 0;
        if (c0 >= 0) L = lvl[c0] + 1;
        if (c1 >= 0) L = max(L, lvl[c1] + 1);
        lvl[t] = L;
        atomicMax(&s_lvl[t], L);
        sp += 1 - abs(a);
        if (sp < 0) sp = 0;
        if (sp > TN + 1) sp = TN + 1;
        if (a != -1) stck[sp] = t;
    }
    g_root[b] = stck[max(sp, 0)];
    __syncthreads();

    if (b < TN) {
        atomicMax(&s_max, s_lvl[b]);
        atomicAdd(&s_cur[s_lvl[b]], 1);
    }
    __syncthreads();
    if (b == 0) {
        int nl = s_max + 1;
        int pos = 0;
        for (int L = 0; L < nl; L++) {
            s_start[L] = pos;
            g_lvlstart[L] = pos;
            pos += s_cur[L];
            s_cur[L] = 0;
        }
        g_lvlstart[nl] = pos;
        g_numlevels = nl;
    }
    __syncthreads();
    if (b < TN) {
        int L = s_lvl[b];
        int p = atomicAdd(&s_cur[L], 1);
        g_order[s_start[L] + p] = b;
    }
}

// -------- grid barrier --------
__device__ __forceinline__ void grid_sync(unsigned& target) {
    __syncthreads();
    if (threadIdx.x == 0) {
        __threadfence();
        atomicAdd(&g_barcnt, 1u);
        volatile unsigned* p = &g_barcnt;
        while (*p < target) { __nanosleep(32); }
        __threadfence();
    }
    __syncthreads();
    target += gridDim.x;
}

// -------- persistent fused kernel --------
// Task = (step t, btile 0..3, ntile 0..7): out tile 128 rows x 96 gate-cols (32 m x 3 gates),
// K = 640 fused [x | h_c0 | h_c1] (128 if no children). Fused LSTM epilogue writes h directly.
// 3-stage cp.async pipeline, one __syncthreads per chunk.
__global__ __launch_bounds__(256, 2) void persist_kernel(float* __restrict__ hmem) {
    extern __shared__ __align__(16) char dyn[];
    __shared__ int c0s[128];
    __shared__ int c1s[128];
    __shared__ float bcs[NW];
    int tid = threadIdx.x;
    int lane = tid & 31;
    int w = tid >> 5;
    int wm = w >> 1;
    int wn = w & 1;
    int g = lane >> 2;
    int tig = lane & 3;
    unsigned target = gridDim.x;

    uint32_t ubase = smem_u32(dyn);
    int arow = lane & 15;
    int ak8 = (lane >> 4) << 3;
    int bnrow = (lane & 7) + ((lane >> 4) << 3);
    int bk8 = ((lane >> 3) & 1) << 3;
    float* Xs = (float*)dyn;   // exchange buffer aliases pipeline stages 0..1

    int nlev = g_numlevels;
    for (int L = 0; L < nlev; L++) {
        int s0 = g_lvlstart[L];
        int ntasks = (g_lvlstart[L + 1] - s0) * 32;
        for (int task = blockIdx.x; task < ntasks; task += gridDim.x) {
            int t = g_order[s0 + (task >> 5)];
            int sub = task & 31;
            int btile = (sub & 3) * 128;
            int ntb = (sub >> 2) * NW;
            int m0 = (sub >> 2) * 32;

            __syncthreads();   // protect Xs / c0s from previous task
            if (tid < 128) {
                c0s[tid] = g_child0[t * BN + btile + tid];
                c1s[tid] = g_child1[t * BN + btile + tid];
            }
            if (tid < NW) bcs[tid] = g_bc[ntb + tid];
            __syncthreads();
            int act = __syncthreads_or((tid < 128) ? ((c0s[tid] >= 0) | (c1s[tid] >= 0)) : 0);
            int nch = act ? (KC / 32) : (INN / 32);

            float d[2][6][4];
            #pragma unroll
            for (int i = 0; i < 2; i++)
                #pragma unroll
                for (int j = 0; j < 6; j++)
                    #pragma unroll
                    for (int q = 0; q < 4; q++) d[i][j][q] = 0.f;

            // ---- fill one 32-k chunk into stage (ch % NSTAGE) ----
            auto fill = [&](int ch) {
                int kc = ch * 32;
                uint32_t sb = ubase + (uint32_t)(ch % NSTAGE) * STG;
                #pragma unroll
                for (int j = 0; j < 2; j++) {
                    int id = tid + j * 256;
                    int row = id >> 2;
                    int seg = id & 3;
                    uint32_t doff = (uint32_t)(row * SP + seg * 8) * 2;
                    const __nv_bfloat16* sh;
                    const __nv_bfloat16* sl;
                    int sz = 16;
                    if (kc < INN) {
                        size_t o = ((size_t)t * BN + btile + row) * INN + kc + seg * 8;
                        sh = g_Xhi + o;
                        sl = g_Xlo + o;
                    } else {
                        int c = (kc < INN + MN) ? c0s[row] : c1s[row];
                        size_t o = 0;
                        if (c >= 0) {
                            int col = ((kc - INN) & (MN - 1)) + seg * 8;
                            o = ((size_t)c * BN + btile + row) * MN + col;
                        } else {
                            sz = 0;
                        }
                        sh = g_Hhi + o;
                        sl = g_Hlo + o;
                    }
                    cpa16(sb + doff, sh, sz);
                    cpa16(sb + 10240 + doff, sl, sz);
                }
                #pragma unroll
                for (int j = 0; j < 2; j++) {
                    int id = tid + j * 256;
                    if (id < 384) {
                        int row = id >> 2;
                        int seg = id & 3;
                        uint32_t doff = (uint32_t)(row * SP + seg * 8) * 2;
                        size_t o = (size_t)(ntb + row) * KC + kc + seg * 8;
                        cpa16(sb + 20480 + doff, g_Wchi + o, 16);
                        cpa16(sb + 28160 + doff, g_Wclo + o, 16);
                    }
                }
                cpa_commit();
            };

            // prologue: 2 stages in flight
            fill(0);
            fill(1);
            for (int ch = 0; ch < nch; ch++) {
                if (ch + 1 < nch) cpa_wait1(); else cpa_wait0();
                __syncthreads();              // stage ch visible; closes compute(ch-1)
                if (ch + 2 < nch) fill(ch + 2);   // writes stage (ch-1)%3 — safe
                uint32_t sb = ubase + (uint32_t)(ch % NSTAGE) * STG;
                uint32_t uA = sb;
                uint32_t uAl = sb + 10240;
                uint32_t uB = sb + 20480;
                uint32_t uBl = sb + 28160;
                #pragma unroll
                for (int s16 = 0; s16 < 2; s16++) {
                    int k0 = s16 * 16;
                    uint32_t ah[2][4];
                    uint32_t al[2][4];
                    uint32_t bh[3][4];
                    uint32_t bl[3][4];
                    #pragma unroll
                    for (int mt = 0; mt < 2; mt++) {
                        uint32_t off = (uint32_t)(((wm * 32 + mt * 16 + arow) * SP + k0 + ak8) * 2);
                        ldsm4(ah[mt], uA + off);
                        ldsm4(al[mt], uAl + off);
                    }
                    #pragma unroll
                    for (int p = 0; p < 3; p++) {
                        uint32_t off = (uint32_t)(((wn * 48 + p * 16 + bnrow) * SP + k0 + bk8) * 2);
                        ldsm4(bh[p], uB + off);
                        ldsm4(bl[p], uBl + off);
                    }
                    #pragma unroll
                    for (int mt = 0; mt < 2; mt++) {
                        #pragma unroll
                        for (int p = 0; p < 3; p++) {
                            #pragma unroll
                            for (int q = 0; q < 2; q++) {
                                int nt = p * 2 + q;
                                mma16816(d[mt][nt], ah[mt], &bh[p][q * 2]);
                                mma16816(d[mt][nt], ah[mt], &bl[p][q * 2]);
                                mma16816(d[mt][nt], al[mt], &bh[p][q * 2]);
                            }
                        }
                    }
                }
            }
            __syncthreads();   // all computes done before Xs overwrite

            // ---- exchange: accum -> smem (stride 99) ----
            #pragma unroll
            for (int mt = 0; mt < 2; mt++) {
                #pragma unroll
                for (int nt = 0; nt < 6; nt++) {
                    int r0 = wm * 32 + mt * 16 + g;
                    int c0 = wn * 48 + nt * 8 + tig * 2;
                    Xs[r0 * 99 + c0] = d[mt][nt][0];
                    Xs[r0 * 99 + c0 + 1] = d[mt][nt][1];
                    Xs[(r0 + 8) * 99 + c0] = d[mt][nt][2];
                    Xs[(r0 + 8) * 99 + c0 + 1] = d[mt][nt][3];
                }
            }
            __syncthreads();

            // ---- fused LSTM epilogue: 2 threads per row, 16 m each ----
            {
                int row = tid >> 1;
                int mh = (tid & 1) * 16;
                float hv[16];
                #pragma unroll
                for (int mm = 0; mm < 16; mm++) {
                    int mj = mh + mm;
                    float vi = Xs[row * 99 + mj * 3 + 0] + bcs[mj * 3 + 0];
                    float vo = Xs[row * 99 + mj * 3 + 1] + bcs[mj * 3 + 1];
                    float vu = Xs[row * 99 + mj * 3 + 2] + bcs[mj * 3 + 2];
                    float cc = sigf(vi) * tanhf(vu);
                    hv[mm] = sigf(vo) * tanhf(cc);
                }
                size_t base = ((size_t)t * BN + btile + row) * MN + m0 + mh;
                #pragma unroll
                for (int q = 0; q < 4; q++) {
                    *(float4*)(hmem + base + q * 4) =
                        make_float4(hv[q * 4], hv[q * 4 + 1], hv[q * 4 + 2], hv[q * 4 + 3]);
                }
                uint32_t ph[8];
                uint32_t pl[8];
                #pragma unroll
                for (int q = 0; q < 8; q++) {
                    float h0 = hv[q * 2];
                    float h1 = hv[q * 2 + 1];
                    __nv_bfloat16 b0 = __float2bfloat16_rn(h0);
                    __nv_bfloat16 b1 = __float2bfloat16_rn(h1);
                    float f0 = __bfloat162float(b0);
                    float f1 = __bfloat162float(b1);
                    ph[q] = packbf2(f0, f1);
                    pl[q] = packbf2(h0 - f0, h1 - f1);
                }
                *(uint4*)(g_Hhi + base) = make_uint4(ph[0], ph[1], ph[2], ph[3]);
                *(uint4*)(g_Hhi + base + 8) = make_uint4(ph[4], ph[5], ph[6], ph[7]);
                *(uint4*)(g_Hlo + base) = make_uint4(pl[0], pl[1], pl[2], pl[3]);
                *(uint4*)(g_Hlo + base + 8) = make_uint4(pl[4], pl[5], pl[6], pl[7]);
            }
        }
        grid_sync(target);
    }
}

// -------- root gather --------
__global__ void root_kernel(float* __restrict__ out, const float* __restrict__ hmem) {
    int b = blockIdx.x;
    int m = threadIdx.x;
    out[b * MN + m] = hmem[((size_t)g_root[b] * BN + b) * MN + m];
}

extern "C" void kernel_launch(void* const* d_in, const int* in_sizes, int n_in,
                              void* d_out, int out_size) {
    const float* X  = (const float*)d_in[0];
    const int*   ar = (const int*)  d_in[1];
    const float* Wi = (const float*)d_in[2];
    const float* bi = (const float*)d_in[3];
    const float* Wo = (const float*)d_in[4];
    const float* bo = (const float*)d_in[5];
    const float* Wu = (const float*)d_in[6];
    const float* bu = (const float*)d_in[7];
    const float* Ui = (const float*)d_in[10];
    const float* Uo = (const float*)d_in[11];
    const float* Uu = (const float*)d_in[12];

    float* out  = (float*)d_out;
    float* hmem = out + BN * MN;

    cudaFuncSetAttribute(persist_kernel, cudaFuncAttributeMaxDynamicSharedMemorySize, DSM);

    prep_kernel<<<512, 256>>>(X, Wi, bi, Wo, bo, Wu, bu, Ui, Uo, Uu);
    sched_kernel<<<1, BN>>>(ar);
    persist_kernel<<<GRID_P, 256, DSM>>>(hmem);
    root_kernel<<<BN, MN>>>(out, hmem);
}

// round 11
// speedup vs baseline: 1.1007x; 1.1007x over previous
#include <cuda_runtime.h>
#include <cuda_bf16.h>
#include <math.h>
#include <stdint.h>

#define TN  256
#define BN  512
#define INN 128
#define MN  256
#define KC  640          // fused K: 128 x + 2*256 children
#define NW  96           // N tile: 32 m * 3 gates
#define GRID_P 296
#define SP  40           // padded smem row stride (bf16)

// dynamic smem: 2 stages * 35840B; stage: Ahi 0, Alo 10240, Bhi 20480, Blo 28160
#define STG 35840
#define DSM (2 * STG)

// -------- device scratch --------
__device__ __nv_bfloat16 g_Wchi[768 * KC];
__device__ __nv_bfloat16 g_Wclo[768 * KC];
__device__ __nv_bfloat16 g_Xhi[(size_t)TN * BN * INN];
__device__ __nv_bfloat16 g_Xlo[(size_t)TN * BN * INN];
__device__ __nv_bfloat16 g_Hhi[(size_t)TN * BN * MN];
__device__ __nv_bfloat16 g_Hlo[(size_t)TN * BN * MN];
__device__ float g_bc[768];
__device__ int   g_child0[TN * BN];
__device__ int   g_child1[TN * BN];
__device__ int   g_root[BN];
__device__ int   g_order[TN];
__device__ int   g_lvl[TN];
__device__ int   g_lvlstart[TN + 2];
__device__ int   g_numlevels;
__device__ unsigned g_barcnt;

__device__ __forceinline__ float sigf(float x) { return 1.0f / (1.0f + expf(-x)); }

__device__ __forceinline__ uint32_t smem_u32(const void* p) {
    uint32_t a;
    asm("{ .reg .u64 t; cvta.to.shared.u64 t, %1; cvt.u32.u64 %0, t; }" : "=r"(a) : "l"(p));
    return a;
}

__device__ __forceinline__ void mma16816(float* d, const uint32_t* a, const uint32_t* b) {
    asm volatile(
        "mma.sync.aligned.m16n8k16.row.col.f32.bf16.bf16.f32 "
        "{%0,%1,%2,%3}, {%4,%5,%6,%7}, {%8,%9}, {%0,%1,%2,%3};"
        : "+f"(d[0]), "+f"(d[1]), "+f"(d[2]), "+f"(d[3])
        : "r"(a[0]), "r"(a[1]), "r"(a[2]), "r"(a[3]), "r"(b[0]), "r"(b[1]));
}

__device__ __forceinline__ void ldsm4(uint32_t* r, uint32_t addr) {
    asm volatile("ldmatrix.sync.aligned.m8n8.x4.shared.b16 {%0,%1,%2,%3}, [%4];"
                 : "=r"(r[0]), "=r"(r[1]), "=r"(r[2]), "=r"(r[3]) : "r"(addr));
}

// streaming copy: bypass L1 (cg), 16B granule, src-size form for zero-fill
__device__ __forceinline__ void cpa16(uint32_t dst, const void* src, int sz) {
    asm volatile("cp.async.cg.shared.global [%0], [%1], 16, %2;"
                 :: "r"(dst), "l"(src), "r"(sz) : "memory");
}
__device__ __forceinline__ void cpa_commit() {
    asm volatile("cp.async.commit_group;" ::: "memory");
}
__device__ __forceinline__ void cpa_wait1() {
    asm volatile("cp.async.wait_group 1;" ::: "memory");
}
__device__ __forceinline__ void cpa_wait0() {
    asm volatile("cp.async.wait_group 0;" ::: "memory");
}

__device__ __forceinline__ uint32_t packbf2(float x, float y) {
    __nv_bfloat162 v = __floats2bfloat162_rn(x, y);
    return *reinterpret_cast<uint32_t*>(&v);
}

// -------- prep: X split, fused interleaved weights, bias, sched init --------
__global__ void prep_kernel(const float* __restrict__ X,
                            const float* __restrict__ Wi, const float* __restrict__ bi,
                            const float* __restrict__ Wo, const float* __restrict__ bo,
                            const float* __restrict__ Wu, const float* __restrict__ bu,
                            const float* __restrict__ Ui, const float* __restrict__ Uo,
                            const float* __restrict__ Uu) {
    size_t idx = blockIdx.x * blockDim.x + threadIdx.x;
    size_t stride = (size_t)gridDim.x * blockDim.x;
    if (idx == 0) g_barcnt = 0u;
    for (size_t i = idx; i < TN; i += stride) g_lvl[i] = 0;
    for (size_t i = idx; i < (size_t)TN * BN * INN; i += stride) {
        float x = X[i];
        __nv_bfloat16 h = __float2bfloat16_rn(x);
        g_Xhi[i] = h;
        g_Xlo[i] = __float2bfloat16_rn(x - __bfloat162float(h));
    }
    for (size_t i = idx; i < (size_t)768 * KC; i += stride) {
        int n = (int)(i / KC);
        int k = (int)(i % KC);
        int m = n / 3;
        int g = n % 3;
        float x;
        if (k < INN) {
            const float* W = (g == 0) ? Wi : ((g == 1) ? Wo : Wu);
            x = W[m * INN + k];
        } else {
            const float* U = (g == 0) ? Ui : ((g == 1) ? Uo : Uu);
            int br = (k - INN) / MN;
            int kk = (k - INN) % MN;
            x = U[br * MN * MN + m * MN + kk];
        }
        __nv_bfloat16 h = __float2bfloat16_rn(x);
        g_Wchi[i] = h;
        g_Wclo[i] = __float2bfloat16_rn(x - __bfloat162float(h));
    }
    for (size_t i = idx; i < 768; i += stride) {
        int m = (int)i / 3;
        int g = (int)i % 3;
        const float* bb = (g == 0) ? bi : ((g == 1) ? bo : bu);
        g_bc[i] = bb[m];
    }
}

// -------- scheduler A: per-tree stack sim, 16 blocks x 32 trees --------
__global__ void sched_a_kernel(const int* __restrict__ arities) {
    int b = blockIdx.x * 32 + threadIdx.x;
    int stck[TN + 2];
    int lvl[TN];
    for (int i = 0; i < TN + 2; i++) stck[i] = 0;
    int sp = 1;
    for (int t = 0; t < TN; t++) {
        int a = arities[t * BN + b];
        int c0 = -1;
        int c1 = -1;
        if (a > 0) {
            int s = stck[max(sp, 0)];
            if (s < t) c0 = s;
        }
        if (a > 1) {
            int s = stck[max(sp - 1, 0)];
            if (s < t) c1 = s;
        }
        g_child0[t * BN + b] = c0;
        g_child1[t * BN + b] = c1;
        int L = 0;
        if (c0 >= 0) L = lvl[c0] + 1;
        if (c1 >= 0) L = max(L, lvl[c1] + 1);
        lvl[t] = L;
        atomicMax(&g_lvl[t], L);
        sp += 1 - abs(a);
        if (sp < 0) sp = 0;
        if (sp > TN + 1) sp = TN + 1;
        if (a != -1) stck[sp] = t;
    }
    g_root[b] = stck[max(sp, 0)];
}

// -------- scheduler B: level histogram + wavefront order (1 block) --------
__global__ void sched_b_kernel() {
    __shared__ int s_start[TN + 1];
    __shared__ int s_cur[TN + 1];
    __shared__ int s_max;
    int i = threadIdx.x;  // 256 threads
    s_cur[i] = 0;
    if (i == 0) { s_max = 0; s_cur[TN] = 0; }
    __syncthreads();
    int L = g_lvl[i];
    atomicMax(&s_max, L);
    atomicAdd(&s_cur[L], 1);
    __syncthreads();
    if (i == 0) {
        int nl = s_max + 1;
        int pos = 0;
        for (int q = 0; q < nl; q++) {
            s_start[q] = pos;
            g_lvlstart[q] = pos;
            pos += s_cur[q];
            s_cur[q] = 0;
        }
        g_lvlstart[nl] = pos;
        g_numlevels = nl;
    }
    __syncthreads();
    int p = atomicAdd(&s_cur[L], 1);
    g_order[s_start[L] + p] = i;
}

// -------- grid barrier --------
__device__ __forceinline__ void grid_sync(unsigned& target) {
    __syncthreads();
    if (threadIdx.x == 0) {
        __threadfence();
        atomicAdd(&g_barcnt, 1u);
        volatile unsigned* p = &g_barcnt;
        while (*p < target) { __nanosleep(32); }
        __threadfence();
    }
    __syncthreads();
    target += gridDim.x;
}

// -------- persistent fused kernel (R8-proven 2-stage pipeline) --------
__global__ __launch_bounds__(256, 2) void persist_kernel(float* __restrict__ hmem) {
    extern __shared__ __align__(16) char dyn[];
    __shared__ int c0s[128];
    __shared__ int c1s[128];
    __shared__ float bcs[NW];
    int tid = threadIdx.x;
    int lane = tid & 31;
    int w = tid >> 5;
    int wm = w >> 1;
    int wn = w & 1;
    int g = lane >> 2;
    int tig = lane & 3;
    unsigned target = gridDim.x;

    uint32_t ubase = smem_u32(dyn);
    int arow = lane & 15;
    int ak8 = (lane >> 4) << 3;
    int bnrow = (lane & 7) + ((lane >> 4) << 3);
    int bk8 = ((lane >> 3) & 1) << 3;
    float* Xs = (float*)dyn;

    int nlev = g_numlevels;
    for (int L = 0; L < nlev; L++) {
        int s0 = g_lvlstart[L];
        int ntasks = (g_lvlstart[L + 1] - s0) * 32;
        for (int task = blockIdx.x; task < ntasks; task += gridDim.x) {
            int t = g_order[s0 + (task >> 5)];
            int sub = task & 31;
            int btile = (sub & 3) * 128;
            int ntb = (sub >> 2) * NW;
            int m0 = (sub >> 2) * 32;

            __syncthreads();
            if (tid < 128) {
                c0s[tid] = g_child0[t * BN + btile + tid];
                c1s[tid] = g_child1[t * BN + btile + tid];
            }
            if (tid < NW) bcs[tid] = g_bc[ntb + tid];
            __syncthreads();
            int act = __syncthreads_or((tid < 128) ? ((c0s[tid] >= 0) | (c1s[tid] >= 0)) : 0);
            int nch = act ? (KC / 32) : (INN / 32);

            float d[2][6][4];
            #pragma unroll
            for (int i = 0; i < 2; i++)
                #pragma unroll
                for (int j = 0; j < 6; j++)
                    #pragma unroll
                    for (int q = 0; q < 4; q++) d[i][j][q] = 0.f;

            auto fill = [&](int ch) {
                int kc = ch * 32;
                uint32_t sb = ubase + (uint32_t)(ch & 1) * STG;
                #pragma unroll
                for (int j = 0; j < 2; j++) {
                    int id = tid + j * 256;
                    int row = id >> 2;
                    int seg = id & 3;
                    uint32_t doff = (uint32_t)(row * SP + seg * 8) * 2;
                    const __nv_bfloat16* sh;
                    const __nv_bfloat16* sl;
                    int sz = 16;
                    if (kc < INN) {
                        size_t o = ((size_t)t * BN + btile + row) * INN + kc + seg * 8;
                        sh = g_Xhi + o;
                        sl = g_Xlo + o;
                    } else {
                        int c = (kc < INN + MN) ? c0s[row] : c1s[row];
                        size_t o = 0;
                        if (c >= 0) {
                            int col = ((kc - INN) & (MN - 1)) + seg * 8;
                            o = ((size_t)c * BN + btile + row) * MN + col;
                        } else {
                            sz = 0;
                        }
                        sh = g_Hhi + o;
                        sl = g_Hlo + o;
                    }
                    cpa16(sb + doff, sh, sz);
                    cpa16(sb + 10240 + doff, sl, sz);
                }
                #pragma unroll
                for (int j = 0; j < 2; j++) {
                    int id = tid + j * 256;
                    if (id < 384) {
                        int row = id >> 2;
                        int seg = id & 3;
                        uint32_t doff = (uint32_t)(row * SP + seg * 8) * 2;
                        size_t o = (size_t)(ntb + row) * KC + kc + seg * 8;
                        cpa16(sb + 20480 + doff, g_Wchi + o, 16);
                        cpa16(sb + 28160 + doff, g_Wclo + o, 16);
                    }
                }
                cpa_commit();
            };

            fill(0);
            for (int ch = 0; ch < nch; ch++) {
                if (ch + 1 < nch) {
                    fill(ch + 1);
                    cpa_wait1();
                } else {
                    cpa_wait0();
                }
                __syncthreads();
                uint32_t sb = ubase + (uint32_t)(ch & 1) * STG;
                uint32_t uA = sb;
                uint32_t uAl = sb + 10240;
                uint32_t uB = sb + 20480;
                uint32_t uBl = sb + 28160;
                #pragma unroll
                for (int s16 = 0; s16 < 2; s16++) {
                    int k0 = s16 * 16;
                    uint32_t ah[2][4];
                    uint32_t al[2][4];
                    uint32_t bh[3][4];
                    uint32_t bl[3][4];
                    #pragma unroll
                    for (int mt = 0; mt < 2; mt++) {
                        uint32_t off = (uint32_t)(((wm * 32 + mt * 16 + arow) * SP + k0 + ak8) * 2);
                        ldsm4(ah[mt], uA + off);
                        ldsm4(al[mt], uAl + off);
                    }
                    #pragma unroll
                    for (int p = 0; p < 3; p++) {
                        uint32_t off = (uint32_t)(((wn * 48 + p * 16 + bnrow) * SP + k0 + bk8) * 2);
                        ldsm4(bh[p], uB + off);
                        ldsm4(bl[p], uBl + off);
                    }
                    #pragma unroll
                    for (int mt = 0; mt < 2; mt++) {
                        #pragma unroll
                        for (int p = 0; p < 3; p++) {
                            #pragma unroll
                            for (int q = 0; q < 2; q++) {
                                int nt = p * 2 + q;
                                mma16816(d[mt][nt], ah[mt], &bh[p][q * 2]);
                                mma16816(d[mt][nt], ah[mt], &bl[p][q * 2]);
                                mma16816(d[mt][nt], al[mt], &bh[p][q * 2]);
                            }
                        }
                    }
                }
                __syncthreads();
            }

            // ---- exchange: accum -> smem (stride 99) ----
            #pragma unroll
            for (int mt = 0; mt < 2; mt++) {
                #pragma unroll
                for (int nt = 0; nt < 6; nt++) {
                    int r0 = wm * 32 + mt * 16 + g;
                    int c0 = wn * 48 + nt * 8 + tig * 2;
                    Xs[r0 * 99 + c0] = d[mt][nt][0];
                    Xs[r0 * 99 + c0 + 1] = d[mt][nt][1];
                    Xs[(r0 + 8) * 99 + c0] = d[mt][nt][2];
                    Xs[(r0 + 8) * 99 + c0 + 1] = d[mt][nt][3];
                }
            }
            __syncthreads();

            // ---- fused LSTM epilogue ----
            {
                int row = tid >> 1;
                int mh = (tid & 1) * 16;
                float hv[16];
                #pragma unroll
                for (int mm = 0; mm < 16; mm++) {
                    int mj = mh + mm;
                    float vi = Xs[row * 99 + mj * 3 + 0] + bcs[mj * 3 + 0];
                    float vo = Xs[row * 99 + mj * 3 + 1] + bcs[mj * 3 + 1];
                    float vu = Xs[row * 99 + mj * 3 + 2] + bcs[mj * 3 + 2];
                    float cc = sigf(vi) * tanhf(vu);
                    hv[mm] = sigf(vo) * tanhf(cc);
                }
                size_t base = ((size_t)t * BN + btile + row) * MN + m0 + mh;
                #pragma unroll
                for (int q = 0; q < 4; q++) {
                    *(float4*)(hmem + base + q * 4) =
                        make_float4(hv[q * 4], hv[q * 4 + 1], hv[q * 4 + 2], hv[q * 4 + 3]);
                }
                uint32_t ph[8];
                uint32_t pl[8];
                #pragma unroll
                for (int q = 0; q < 8; q++) {
                    float h0 = hv[q * 2];
                    float h1 = hv[q * 2 + 1];
                    __nv_bfloat16 b0 = __float2bfloat16_rn(h0);
                    __nv_bfloat16 b1 = __float2bfloat16_rn(h1);
                    float f0 = __bfloat162float(b0);
                    float f1 = __bfloat162float(b1);
                    ph[q] = packbf2(f0, f1);
                    pl[q] = packbf2(h0 - f0, h1 - f1);
                }
                *(uint4*)(g_Hhi + base) = make_uint4(ph[0], ph[1], ph[2], ph[3]);
                *(uint4*)(g_Hhi + base + 8) = make_uint4(ph[4], ph[5], ph[6], ph[7]);
                *(uint4*)(g_Hlo + base) = make_uint4(pl[0], pl[1], pl[2], pl[3]);
                *(uint4*)(g_Hlo + base + 8) = make_uint4(pl[4], pl[5], pl[6], pl[7]);
            }
        }
        grid_sync(target);
    }
}

// -------- root gather --------
__global__ void root_kernel(float* __restrict__ out, const float* __restrict__ hmem) {
    int b = blockIdx.x;
    int m = threadIdx.x;
    out[b * MN + m] = hmem[((size_t)g_root[b] * BN + b) * MN + m];
}

extern "C" void kernel_launch(void* const* d_in, const int* in_sizes, int n_in,
                              void* d_out, int out_size) {
    const float* X  = (const float*)d_in[0];
    const int*   ar = (const int*)  d_in[1];
    const float* Wi = (const float*)d_in[2];
    const float* bi = (const float*)d_in[3];
    const float* Wo = (const float*)d_in[4];
    const float* bo = (const float*)d_in[5];
    const float* Wu = (const float*)d_in[6];
    const float* bu = (const float*)d_in[7];
    const float* Ui = (const float*)d_in[10];
    const float* Uo = (const float*)d_in[11];
    const float* Uu = (const float*)d_in[12];

    float* out  = (float*)d_out;
    float* hmem = out + BN * MN;

    cudaFuncSetAttribute(persist_kernel, cudaFuncAttributeMaxDynamicSharedMemorySize, DSM);

    prep_kernel<<<512, 256>>>(X, Wi, bi, Wo, bo, Wu, bu, Ui, Uo, Uu);
    sched_a_kernel<<<16, 32>>>(ar);
    sched_b_kernel<<<1, 256>>>();
    persist_kernel<<<GRID_P, 256, DSM>>>(hmem);
    root_kernel<<<BN, MN>>>(out, hmem);
}

// round 12
// speedup vs baseline: 1.1806x; 1.0726x over previous
#include <cuda_runtime.h>
#include <cuda_bf16.h>
#include <math.h>
#include <stdint.h>

#define TN  256
#define BN  512
#define INN 128
#define MN  256
#define KC  640          // fused K: 128 x + 2*256 children
#define NW  96           // N tile: 32 m * 3 gates
#define GRID_P 296
#define SP  40           // padded smem row stride (bf16)

// dynamic smem: 2 stages * 35840B; stage: Ahi 0, Alo 10240, Bhi 20480, Blo 28160
#define STG 35840
#define DSM (2 * STG)

// -------- device scratch --------
__device__ __nv_bfloat16 g_Wchi[768 * KC];
__device__ __nv_bfloat16 g_Wclo[768 * KC];
__device__ __nv_bfloat16 g_Xhi[(size_t)TN * BN * INN];
__device__ __nv_bfloat16 g_Xlo[(size_t)TN * BN * INN];
__device__ __nv_bfloat16 g_Hhi[(size_t)TN * BN * MN];
__device__ __nv_bfloat16 g_Hlo[(size_t)TN * BN * MN];
__device__ float g_bc[768];
__device__ int   g_child0[TN * BN];
__device__ int   g_child1[TN * BN];
__device__ int   g_root[BN];
__device__ int   g_order[TN];
__device__ int   g_lvl[TN];
__device__ int   g_lvlstart[TN + 2];
__device__ int   g_numlevels;
__device__ unsigned g_barcnt;

// fast sigmoid / tanh via MUFU (EX2 + approx div). rel err ~1e-6.
__device__ __forceinline__ float sigf(float x) {
    return __fdividef(1.0f, 1.0f + __expf(-x));
}
__device__ __forceinline__ float tanhfast(float x) {
    return 2.0f * __fdividef(1.0f, 1.0f + __expf(-2.0f * x)) - 1.0f;
}

__device__ __forceinline__ uint32_t smem_u32(const void* p) {
    uint32_t a;
    asm("{ .reg .u64 t; cvta.to.shared.u64 t, %1; cvt.u32.u64 %0, t; }" : "=r"(a) : "l"(p));
    return a;
}

__device__ __forceinline__ void mma16816(float* d, const uint32_t* a, const uint32_t* b) {
    asm volatile(
        "mma.sync.aligned.m16n8k16.row.col.f32.bf16.bf16.f32 "
        "{%0,%1,%2,%3}, {%4,%5,%6,%7}, {%8,%9}, {%0,%1,%2,%3};"
        : "+f"(d[0]), "+f"(d[1]), "+f"(d[2]), "+f"(d[3])
        : "r"(a[0]), "r"(a[1]), "r"(a[2]), "r"(a[3]), "r"(b[0]), "r"(b[1]));
}

__device__ __forceinline__ void ldsm4(uint32_t* r, uint32_t addr) {
    asm volatile("ldmatrix.sync.aligned.m8n8.x4.shared.b16 {%0,%1,%2,%3}, [%4];"
                 : "=r"(r[0]), "=r"(r[1]), "=r"(r[2]), "=r"(r[3]) : "r"(addr));
}

__device__ __forceinline__ void cpa16(uint32_t dst, const void* src, int sz) {
    asm volatile("cp.async.ca.shared.global [%0], [%1], 16, %2;"
                 :: "r"(dst), "l"(src), "r"(sz) : "memory");
}
__device__ __forceinline__ void cpa_commit() {
    asm volatile("cp.async.commit_group;" ::: "memory");
}
__device__ __forceinline__ void cpa_wait1() {
    asm volatile("cp.async.wait_group 1;" ::: "memory");
}
__device__ __forceinline__ void cpa_wait0() {
    asm volatile("cp.async.wait_group 0;" ::: "memory");
}

__device__ __forceinline__ uint32_t packbf2(float x, float y) {
    __nv_bfloat162 v = __floats2bfloat162_rn(x, y);
    return *reinterpret_cast<uint32_t*>(&v);
}

// -------- prep: X split, fused interleaved weights, bias, sched init --------
__global__ void prep_kernel(const float* __restrict__ X,
                            const float* __restrict__ Wi, const float* __restrict__ bi,
                            const float* __restrict__ Wo, const float* __restrict__ bo,
                            const float* __restrict__ Wu, const float* __restrict__ bu,
                            const float* __restrict__ Ui, const float* __restrict__ Uo,
                            const float* __restrict__ Uu) {
    size_t idx = blockIdx.x * blockDim.x + threadIdx.x;
    size_t stride = (size_t)gridDim.x * blockDim.x;
    if (idx == 0) g_barcnt = 0u;
    for (size_t i = idx; i < TN; i += stride) g_lvl[i] = 0;
    for (size_t i = idx; i < (size_t)TN * BN * INN; i += stride) {
        float x = X[i];
        __nv_bfloat16 h = __float2bfloat16_rn(x);
        g_Xhi[i] = h;
        g_Xlo[i] = __float2bfloat16_rn(x - __bfloat162float(h));
    }
    for (size_t i = idx; i < (size_t)768 * KC; i += stride) {
        int n = (int)(i / KC);
        int k = (int)(i % KC);
        int m = n / 3;
        int g = n % 3;
        float x;
        if (k < INN) {
            const float* W = (g == 0) ? Wi : ((g == 1) ? Wo : Wu);
            x = W[m * INN + k];
        } else {
            const float* U = (g == 0) ? Ui : ((g == 1) ? Uo : Uu);
            int br = (k - INN) / MN;
            int kk = (k - INN) % MN;
            x = U[br * MN * MN + m * MN + kk];
        }
        __nv_bfloat16 h = __float2bfloat16_rn(x);
        g_Wchi[i] = h;
        g_Wclo[i] = __float2bfloat16_rn(x - __bfloat162float(h));
    }
    for (size_t i = idx; i < 768; i += stride) {
        int m = (int)i / 3;
        int g = (int)i % 3;
        const float* bb = (g == 0) ? bi : ((g == 1) ? bo : bu);
        g_bc[i] = bb[m];
    }
}

// -------- scheduler A: per-tree stack sim, 16 blocks x 32 trees --------
__global__ void sched_a_kernel(const int* __restrict__ arities) {
    int b = blockIdx.x * 32 + threadIdx.x;
    int stck[TN + 2];
    int lvl[TN];
    for (int i = 0; i < TN + 2; i++) stck[i] = 0;
    int sp = 1;
    for (int t = 0; t < TN; t++) {
        int a = arities[t * BN + b];
        int c0 = -1;
        int c1 = -1;
        if (a > 0) {
            int s = stck[max(sp, 0)];
            if (s < t) c0 = s;
        }
        if (a > 1) {
            int s = stck[max(sp - 1, 0)];
            if (s < t) c1 = s;
        }
        g_child0[t * BN + b] = c0;
        g_child1[t * BN + b] = c1;
        int L = 0;
        if (c0 >= 0) L = lvl[c0] + 1;
        if (c1 >= 0) L = max(L, lvl[c1] + 1);
        lvl[t] = L;
        atomicMax(&g_lvl[t], L);
        sp += 1 - abs(a);
        if (sp < 0) sp = 0;
        if (sp > TN + 1) sp = TN + 1;
        if (a != -1) stck[sp] = t;
    }
    g_root[b] = stck[max(sp, 0)];
}

// -------- scheduler B: level histogram + wavefront order (1 block) --------
__global__ void sched_b_kernel() {
    __shared__ int s_start[TN + 1];
    __shared__ int s_cur[TN + 1];
    __shared__ int s_max;
    int i = threadIdx.x;  // 256 threads
    s_cur[i] = 0;
    if (i == 0) { s_max = 0; s_cur[TN] = 0; }
    __syncthreads();
    int L = g_lvl[i];
    atomicMax(&s_max, L);
    atomicAdd(&s_cur[L], 1);
    __syncthreads();
    if (i == 0) {
        int nl = s_max + 1;
        int pos = 0;
        for (int q = 0; q < nl; q++) {
            s_start[q] = pos;
            g_lvlstart[q] = pos;
            pos += s_cur[q];
            s_cur[q] = 0;
        }
        g_lvlstart[nl] = pos;
        g_numlevels = nl;
    }
    __syncthreads();
    int p = atomicAdd(&s_cur[L], 1);
    g_order[s_start[L] + p] = i;
}

// -------- grid barrier --------
__device__ __forceinline__ void grid_sync(unsigned& target) {
    __syncthreads();
    if (threadIdx.x == 0) {
        __threadfence();
        atomicAdd(&g_barcnt, 1u);
        volatile unsigned* p = &g_barcnt;
        while (*p < target) { __nanosleep(32); }
        __threadfence();
    }
    __syncthreads();
    target += gridDim.x;
}

// -------- persistent fused kernel (R8-proven 2-stage pipeline) --------
__global__ __launch_bounds__(256, 2) void persist_kernel(float* __restrict__ hmem) {
    extern __shared__ __align__(16) char dyn[];
    __shared__ int c0s[128];
    __shared__ int c1s[128];
    __shared__ float bcs[NW];
    int tid = threadIdx.x;
    int lane = tid & 31;
    int w = tid >> 5;
    int wm = w >> 1;
    int wn = w & 1;
    int g = lane >> 2;
    int tig = lane & 3;
    unsigned target = gridDim.x;

    uint32_t ubase = smem_u32(dyn);
    int arow = lane & 15;
    int ak8 = (lane >> 4) << 3;
    int bnrow = (lane & 7) + ((lane >> 4) << 3);
    int bk8 = ((lane >> 3) & 1) << 3;
    float* Xs = (float*)dyn;

    int nlev = g_numlevels;
    for (int L = 0; L < nlev; L++) {
        int s0 = g_lvlstart[L];
        int ntasks = (g_lvlstart[L + 1] - s0) * 32;
        for (int task = blockIdx.x; task < ntasks; task += gridDim.x) {
            int t = g_order[s0 + (task >> 5)];
            int sub = task & 31;
            int btile = (sub & 3) * 128;
            int ntb = (sub >> 2) * NW;
            int m0 = (sub >> 2) * 32;

            __syncthreads();
            if (tid < 128) {
                c0s[tid] = g_child0[t * BN + btile + tid];
                c1s[tid] = g_child1[t * BN + btile + tid];
            }
            if (tid < NW) bcs[tid] = g_bc[ntb + tid];
            __syncthreads();
            int act = __syncthreads_or((tid < 128) ? ((c0s[tid] >= 0) | (c1s[tid] >= 0)) : 0);
            int nch = act ? (KC / 32) : (INN / 32);

            float d[2][6][4];
            #pragma unroll
            for (int i = 0; i < 2; i++)
                #pragma unroll
                for (int j = 0; j < 6; j++)
                    #pragma unroll
                    for (int q = 0; q < 4; q++) d[i][j][q] = 0.f;

            auto fill = [&](int ch) {
                int kc = ch * 32;
                uint32_t sb = ubase + (uint32_t)(ch & 1) * STG;
                #pragma unroll
                for (int j = 0; j < 2; j++) {
                    int id = tid + j * 256;
                    int row = id >> 2;
                    int seg = id & 3;
                    uint32_t doff = (uint32_t)(row * SP + seg * 8) * 2;
                    const __nv_bfloat16* sh;
                    const __nv_bfloat16* sl;
                    int sz = 16;
                    if (kc < INN) {
                        size_t o = ((size_t)t * BN + btile + row) * INN + kc + seg * 8;
                        sh = g_Xhi + o;
                        sl = g_Xlo + o;
                    } else {
                        int c = (kc < INN + MN) ? c0s[row] : c1s[row];
                        size_t o = 0;
                        if (c >= 0) {
                            int col = ((kc - INN) & (MN - 1)) + seg * 8;
                            o = ((size_t)c * BN + btile + row) * MN + col;
                        } else {
                            sz = 0;
                        }
                        sh = g_Hhi + o;
                        sl = g_Hlo + o;
                    }
                    cpa16(sb + doff, sh, sz);
                    cpa16(sb + 10240 + doff, sl, sz);
                }
                #pragma unroll
                for (int j = 0; j < 2; j++) {
                    int id = tid + j * 256;
                    if (id < 384) {
                        int row = id >> 2;
                        int seg = id & 3;
                        uint32_t doff = (uint32_t)(row * SP + seg * 8) * 2;
                        size_t o = (size_t)(ntb + row) * KC + kc + seg * 8;
                        cpa16(sb + 20480 + doff, g_Wchi + o, 16);
                        cpa16(sb + 28160 + doff, g_Wclo + o, 16);
                    }
                }
                cpa_commit();
            };

            fill(0);
            for (int ch = 0; ch < nch; ch++) {
                if (ch + 1 < nch) {
                    fill(ch + 1);
                    cpa_wait1();
                } else {
                    cpa_wait0();
                }
                __syncthreads();
                uint32_t sb = ubase + (uint32_t)(ch & 1) * STG;
                uint32_t uA = sb;
                uint32_t uAl = sb + 10240;
                uint32_t uB = sb + 20480;
                uint32_t uBl = sb + 28160;
                #pragma unroll
                for (int s16 = 0; s16 < 2; s16++) {
                    int k0 = s16 * 16;
                    uint32_t ah[2][4];
                    uint32_t al[2][4];
                    uint32_t bh[3][4];
                    uint32_t bl[3][4];
                    #pragma unroll
                    for (int mt = 0; mt < 2; mt++) {
                        uint32_t off = (uint32_t)(((wm * 32 + mt * 16 + arow) * SP + k0 + ak8) * 2);
                        ldsm4(ah[mt], uA + off);
                        ldsm4(al[mt], uAl + off);
                    }
                    #pragma unroll
                    for (int p = 0; p < 3; p++) {
                        uint32_t off = (uint32_t)(((wn * 48 + p * 16 + bnrow) * SP + k0 + bk8) * 2);
                        ldsm4(bh[p], uB + off);
                        ldsm4(bl[p], uBl + off);
                    }
                    #pragma unroll
                    for (int mt = 0; mt < 2; mt++) {
                        #pragma unroll
                        for (int p = 0; p < 3; p++) {
                            #pragma unroll
                            for (int q = 0; q < 2; q++) {
                                int nt = p * 2 + q;
                                mma16816(d[mt][nt], ah[mt], &bh[p][q * 2]);
                                mma16816(d[mt][nt], ah[mt], &bl[p][q * 2]);
                                mma16816(d[mt][nt], al[mt], &bh[p][q * 2]);
                            }
                        }
                    }
                }
                __syncthreads();
            }

            // ---- exchange: accum -> smem (stride 99) ----
            #pragma unroll
            for (int mt = 0; mt < 2; mt++) {
                #pragma unroll
                for (int nt = 0; nt < 6; nt++) {
                    int r0 = wm * 32 + mt * 16 + g;
                    int c0 = wn * 48 + nt * 8 + tig * 2;
                    Xs[r0 * 99 + c0] = d[mt][nt][0];
                    Xs[r0 * 99 + c0 + 1] = d[mt][nt][1];
                    Xs[(r0 + 8) * 99 + c0] = d[mt][nt][2];
                    Xs[(r0 + 8) * 99 + c0 + 1] = d[mt][nt][3];
                }
            }
            __syncthreads();

            // ---- fused LSTM epilogue (fast math) ----
            {
                int row = tid >> 1;
                int mh = (tid & 1) * 16;
                float hv[16];
                #pragma unroll
                for (int mm = 0; mm < 16; mm++) {
                    int mj = mh + mm;
                    float vi = Xs[row * 99 + mj * 3 + 0] + bcs[mj * 3 + 0];
                    float vo = Xs[row * 99 + mj * 3 + 1] + bcs[mj * 3 + 1];
                    float vu = Xs[row * 99 + mj * 3 + 2] + bcs[mj * 3 + 2];
                    float cc = sigf(vi) * tanhfast(vu);
                    hv[mm] = sigf(vo) * tanhfast(cc);
                }
                size_t base = ((size_t)t * BN + btile + row) * MN + m0 + mh;
                #pragma unroll
                for (int q = 0; q < 4; q++) {
                    *(float4*)(hmem + base + q * 4) =
                        make_float4(hv[q * 4], hv[q * 4 + 1], hv[q * 4 + 2], hv[q * 4 + 3]);
                }
                uint32_t ph[8];
                uint32_t pl[8];
                #pragma unroll
                for (int q = 0; q < 8; q++) {
                    float h0 = hv[q * 2];
                    float h1 = hv[q * 2 + 1];
                    __nv_bfloat16 b0 = __float2bfloat16_rn(h0);
                    __nv_bfloat16 b1 = __float2bfloat16_rn(h1);
                    float f0 = __bfloat162float(b0);
                    float f1 = __bfloat162float(b1);
                    ph[q] = packbf2(f0, f1);
                    pl[q] = packbf2(h0 - f0, h1 - f1);
                }
                *(uint4*)(g_Hhi + base) = make_uint4(ph[0], ph[1], ph[2], ph[3]);
                *(uint4*)(g_Hhi + base + 8) = make_uint4(ph[4], ph[5], ph[6], ph[7]);
                *(uint4*)(g_Hlo + base) = make_uint4(pl[0], pl[1], pl[2], pl[3]);
                *(uint4*)(g_Hlo + base + 8) = make_uint4(pl[4], pl[5], pl[6], pl[7]);
            }
        }
        grid_sync(target);
    }
}

// -------- root gather --------
__global__ void root_kernel(float* __restrict__ out, const float* __restrict__ hmem) {
    int b = blockIdx.x;
    int m = threadIdx.x;
    out[b * MN + m] = hmem[((size_t)g_root[b] * BN + b) * MN + m];
}

extern "C" void kernel_launch(void* const* d_in, const int* in_sizes, int n_in,
                              void* d_out, int out_size) {
    const float* X  = (const float*)d_in[0];
    const int*   ar = (const int*)  d_in[1];
    const float* Wi = (const float*)d_in[2];
    const float* bi = (const float*)d_in[3];
    const float* Wo = (const float*)d_in[4];
    const float* bo = (const float*)d_in[5];
    const float* Wu = (const float*)d_in[6];
    const float* bu = (const float*)d_in[7];
    const float* Ui = (const float*)d_in[10];
    const float* Uo = (const float*)d_in[11];
    const float* Uu = (const float*)d_in[12];

    float* out  = (float*)d_out;
    float* hmem = out + BN * MN;

    cudaFuncSetAttribute(persist_kernel, cudaFuncAttributeMaxDynamicSharedMemorySize, DSM);

    prep_kernel<<<512, 256>>>(X, Wi, bi, Wo, bo, Wu, bu, Ui, Uo, Uu);
    sched_a_kernel<<<16, 32>>>(ar);
    sched_b_kernel<<<1, 256>>>();
    persist_kernel<<<GRID_P, 256, DSM>>>(hmem);
    root_kernel<<<BN, MN>>>(out, hmem);
}